// round 14
// baseline (speedup 1.0000x reference)
#include <cuda_runtime.h>
#include <math.h>

#define D_MODEL   64
#define SEQ       4096
#define BATCH_N   256
#define VOCAB     50257
#define PF        8

#define TWOPI_F   6.2831853071795864769f
#define PHI_F     1.6180339887498948482f
#define STEP_F    ((float)(6.283185307179586 / 4096.0))
#define KSCALE    651.8986469044033f          /* 4096 / (2*pi) */
#define MAGIC     12582912.0f                 /* 2^23 + 2^22 */

// Precomputed per-(token, d): (KSCALE/(1+|w|), b*KSCALE), interleaved for LDG.64
__device__ float2 g_A[(size_t)VOCAB * D_MODEL];

__global__ void __launch_bounds__(256)
prep_kernel(const float* __restrict__ emb)
{
    int idx = blockIdx.x * 256 + threadIdx.x;
    if (idx >= VOCAB * D_MODEL) return;
    int tok = idx >> 6;
    int d   = idx & 63;
    float w = emb[(size_t)tok * 128 + d];
    float b = emb[(size_t)tok * 128 + 64 + d];
    float a = __fdividef(KSCALE, __fadd_rn(1.0f, fabsf(w)));
    g_A[idx] = make_float2(a, __fmul_rn(b, KSCALE));
}

// smem: tok[4][4096] 64KB | tphiK[4096] 16KB | h[4][128] 2KB
#define SM_TOK_OFF   0
#define SM_TPHI_OFF  65536
#define SM_H_OFF     81920
#define SM_TOTAL     83968

__global__ void __launch_bounds__(128, 1)
rin_scan_kernel(const int* __restrict__ ids,
                const float* __restrict__ projW,
                const float* __restrict__ projB,
                float* __restrict__ out)
{
    extern __shared__ unsigned char smem[];
    int*    s_tok   = (int*)  (smem + SM_TOK_OFF);    // [4][4096]
    float*  s_tphiK = (float*)(smem + SM_TPHI_OFF);   // [4096]
    float*  s_h     = (float*)(smem + SM_H_OFF);      // [4][128]

    const int tid = threadIdx.x;
    const int sub = tid >> 6;          // 0 or 1: which batch PAIR
    const int d   = tid & 63;
    const int base = blockIdx.x * 4;   // 4 batches per block

    // ---- init ----
    for (int i = tid; i < SEQ; i += 128) {
        s_tphiK[i] = __fmul_rn(fmodf(__fmul_rn((float)i, PHI_F), TWOPI_F), KSCALE);
    }
    for (int bb = 0; bb < 4; bb++) {
        const int* row = ids + (size_t)(base + bb) * SEQ;
        int* st = s_tok + bb * SEQ;
        for (int i = tid; i < SEQ; i += 128) st[i] = row[i];
    }
    __syncthreads();

    const int* stA = s_tok + (sub * 2) * SEQ;       // chain A tokens
    const int* stB = s_tok + (sub * 2 + 1) * SEQ;   // chain B tokens

    // ---- prologue: stage block 0 for both chains ----
    float aA[PF], cA[PF], aB[PF], cB[PF];
#pragma unroll
    for (int j = 0; j < PF; j++) {
        float tp = s_tphiK[j];
        float2 eA = __ldg(&g_A[(size_t)stA[j] * D_MODEL + d]);
        float2 eB = __ldg(&g_A[(size_t)stB[j] * D_MODEL + d]);
        aA[j] = eA.x;  cA[j] = __fadd_rn(eA.y, tp);
        aB[j] = eB.x;  cB[j] = __fadd_rn(eB.y, tp);
    }

    float hrA = 0.0f, hiA = 0.0f;
    float hrB = 0.0f, hiB = 0.0f;

    for (int sb = 0; sb < SEQ; sb += PF) {
        // ---- stage next block (off the chain) ----
        const int sn = (sb + PF) & (SEQ - 1);
        float2 pfA[PF], pfB[PF];
        float  tphn[PF];
#pragma unroll
        for (int j = 0; j < PF; j++) {
            tphn[j] = s_tphiK[sn + j];
            pfA[j]  = __ldg(&g_A[(size_t)stA[sn + j] * D_MODEL + d]);
            pfB[j]  = __ldg(&g_A[(size_t)stB[sn + j] * D_MODEL + d]);
        }

        // ---- two interleaved pure-chain steps ----
#pragma unroll
        for (int j = 0; j < PF; j++) {
            float yrA = __fmaf_rn(hrA, aA[j], cA[j]);
            float yiA = __fmaf_rn(hiA, aA[j], cA[j]);
            float yrB = __fmaf_rn(hrB, aB[j], cB[j]);
            float yiB = __fmaf_rn(hiB, aB[j], cB[j]);

            float frA = __fsub_rn(__fadd_rd(yrA, MAGIC), MAGIC);
            float fiA = __fsub_rn(__fadd_rd(yiA, MAGIC), MAGIC);
            float frB = __fsub_rn(__fadd_rd(yrB, MAGIC), MAGIC);
            float fiB = __fsub_rn(__fadd_rd(yiB, MAGIC), MAGIC);

            float angA = __fmul_rn(__fadd_rn(frA, fiA), STEP_F);
            float angB = __fmul_rn(__fadd_rn(frB, fiB), STEP_F);

            hrA = __cosf(angA);  hiA = __sinf(angA);
            hrB = __cosf(angB);  hiB = __sinf(angB);
        }

        // ---- commit next block's coefficients ----
#pragma unroll
        for (int j = 0; j < PF; j++) {
            aA[j] = pfA[j].x;  cA[j] = __fadd_rn(pfA[j].y, tphn[j]);
            aB[j] = pfB[j].x;  cB[j] = __fadd_rn(pfB[j].y, tphn[j]);
        }
    }

    // ---- write final states ----
    {
        float* shA = s_h + (sub * 2) * 128;
        float* shB = s_h + (sub * 2 + 1) * 128;
        shA[d] = hrA;  shA[64 + d] = hiA;
        shB[d] = hrB;  shB[64 + d] = hiB;
    }
    __syncthreads();

    // ---- projection for all 4 batches ----
    const float* w0 = projW + (size_t)d * 128;
    const float* w1 = projW + (size_t)(d + 64) * 128;
    float bias0 = __ldg(projB + d);
    float bias1 = __ldg(projB + d + 64);
    for (int bb = sub; bb < 4; bb += 2) {
        const float* sh = s_h + bb * 128;
        float acc0 = 0.0f, acc1 = 0.0f;
#pragma unroll 8
        for (int kk = 0; kk < 128; kk++) {
            float hk = sh[kk];
            acc0 = __fmaf_rn(hk, __ldg(w0 + kk), acc0);
            acc1 = __fmaf_rn(hk, __ldg(w1 + kk), acc1);
        }
        out[(size_t)(base + bb) * 128 + d]      = __fadd_rn(acc0, bias0);
        out[(size_t)(base + bb) * 128 + 64 + d] = __fadd_rn(acc1, bias1);
    }
}

extern "C" void kernel_launch(void* const* d_in, const int* in_sizes, int n_in,
                              void* d_out, int out_size)
{
    const int*   ids  = (const int*)d_in[0];     // (256, 4096) int32
    const float* emb  = (const float*)d_in[1];   // (50257, 128) f32
    const float* W    = (const float*)d_in[2];   // (128, 128) f32
    const float* bias = (const float*)d_in[3];   // (128,) f32
    float* out = (float*)d_out;                  // (256, 128) f32

    prep_kernel<<<(VOCAB * D_MODEL + 255) / 256, 256>>>(emb);

    cudaFuncSetAttribute(rin_scan_kernel,
                         cudaFuncAttributeMaxDynamicSharedMemorySize, SM_TOTAL);
    rin_scan_kernel<<<BATCH_N / 4, 128, SM_TOTAL>>>(ids, W, bias, out);
}

// round 15
// speedup vs baseline: 1.3672x; 1.3672x over previous
#include <cuda_runtime.h>
#include <math.h>

#define D_MODEL   64
#define SEQ       4096
#define BATCH_N   256
#define VOCAB     50257
#define PF        8

#define TWOPI_F   6.2831853071795864769f
#define PHI_F     1.6180339887498948482f
#define STEP_F    ((float)(6.283185307179586 / 4096.0))
#define KSCALE    651.8986469044033f          /* 4096 / (2*pi) */
#define MAGIC     12582912.0f                 /* 2^23 + 2^22 */
#define MAGIC2    25165824.0f                 /* 2 * MAGIC */

// Precomputed per-(token, d): (KSCALE/(1+|w|), b*KSCALE), interleaved for LDG.64
__device__ float2 g_A[(size_t)VOCAB * D_MODEL];

__global__ void __launch_bounds__(256)
prep_kernel(const float* __restrict__ emb)
{
    int idx = blockIdx.x * 256 + threadIdx.x;
    if (idx >= VOCAB * D_MODEL) return;
    int tok = idx >> 6;
    int d   = idx & 63;
    float w = emb[(size_t)tok * 128 + d];
    float b = emb[(size_t)tok * 128 + 64 + d];
    float a = __fdividef(KSCALE, __fadd_rn(1.0f, fabsf(w)));
    g_A[idx] = make_float2(a, __fmul_rn(b, KSCALE));
}

// smem: tok[2][4096] 32KB | tphiK[4096] 16KB | h[2][128] 1KB
#define SM_TOK_OFF   0
#define SM_TPHI_OFF  32768
#define SM_H_OFF     49152
#define SM_TOTAL     50176

__global__ void __launch_bounds__(128, 1)
rin_scan_kernel(const int* __restrict__ ids,
                const float* __restrict__ projW,
                const float* __restrict__ projB,
                float* __restrict__ out)
{
    extern __shared__ unsigned char smem[];
    int*    s_tok   = (int*)  (smem + SM_TOK_OFF);    // [2][4096]
    float*  s_tphiK = (float*)(smem + SM_TPHI_OFF);   // [4096]
    float*  s_h     = (float*)(smem + SM_H_OFF);      // [2][128]

    const int tid = threadIdx.x;
    const int sub = tid >> 6;
    const int d   = tid & 63;
    const int batch = blockIdx.x * 2 + sub;

    // ---- init ----
    for (int i = tid; i < SEQ; i += 128) {
        s_tphiK[i] = __fmul_rn(fmodf(__fmul_rn((float)i, PHI_F), TWOPI_F), KSCALE);
    }
    {
        const int* row = ids + (size_t)batch * SEQ;
        int* st = s_tok + sub * SEQ;
        for (int i = d; i < SEQ; i += 64) st[i] = row[i];
    }
    __syncthreads();

    const int* st = s_tok + sub * SEQ;

    // ---- prologue: stage block 0 coefficients ----
    float a_cur[PF], c_cur[PF];
#pragma unroll
    for (int j = 0; j < PF; j++) {
        float2 e = __ldg(&g_A[(size_t)st[j] * D_MODEL + d]);
        a_cur[j] = e.x;
        c_cur[j] = __fadd_rn(e.y, s_tphiK[j]);
    }

    float hr = 0.0f, hi = 0.0f;   // h = (cos, sin) of tracked LUT phase

    for (int sb = 0; sb < SEQ; sb += PF) {
        // ---- stage next block's data (off the chain) ----
        const int sn = (sb + PF) & (SEQ - 1);
        float2 pfn[PF];
        float  tphn[PF];
#pragma unroll
        for (int j = 0; j < PF; j++) {
            tphn[j] = s_tphiK[sn + j];
            pfn[j]  = __ldg(&g_A[(size_t)st[sn + j] * D_MODEL + d]);
        }

        // ---- pure-chain inner steps ----
#pragma unroll
        for (int j = 0; j < PF; j++) {
            float yr = __fmaf_rn(hr, a_cur[j], c_cur[j]);       // theta_r in bins
            float yi = __fmaf_rn(hi, a_cur[j], c_cur[j]);
            float Yr = __fadd_rd(yr, MAGIC);                    // M + floor(yr)
            float Yi = __fadd_rd(yi, MAGIC);                    // M + floor(yi)
            float t  = __fsub_rn(Yi, MAGIC2);                   // floor(yi) - M, exact, || with Yr
            float S  = __fadd_rn(Yr, t);                        // floor(yr)+floor(yi), exact
            float ang = __fmul_rn(S, STEP_F);                   // sin period absorbs mod 4096
            __sincosf(ang, &hi, &hr);                           // shared reduction, 2x MUFU
        }

        // ---- commit next block's coefficients ----
#pragma unroll
        for (int j = 0; j < PF; j++) {
            a_cur[j] = pfn[j].x;
            c_cur[j] = __fadd_rn(pfn[j].y, tphn[j]);
        }
    }

    // ---- projection: out[b,n] = sum_k h[k]*W[n,k] + bias[n] ----
    float* sh = s_h + sub * 128;
    sh[d] = hr;
    sh[64 + d] = hi;
    __syncthreads();

    float acc0 = 0.0f, acc1 = 0.0f;
    const float* w0 = projW + (size_t)d * 128;
    const float* w1 = projW + (size_t)(d + 64) * 128;
#pragma unroll 8
    for (int kk = 0; kk < 128; kk++) {
        float hk = sh[kk];
        acc0 = __fmaf_rn(hk, __ldg(w0 + kk), acc0);
        acc1 = __fmaf_rn(hk, __ldg(w1 + kk), acc1);
    }
    out[(size_t)batch * 128 + d]      = __fadd_rn(acc0, __ldg(projB + d));
    out[(size_t)batch * 128 + 64 + d] = __fadd_rn(acc1, __ldg(projB + d + 64));
}

extern "C" void kernel_launch(void* const* d_in, const int* in_sizes, int n_in,
                              void* d_out, int out_size)
{
    const int*   ids  = (const int*)d_in[0];     // (256, 4096) int32
    const float* emb  = (const float*)d_in[1];   // (50257, 128) f32
    const float* W    = (const float*)d_in[2];   // (128, 128) f32
    const float* bias = (const float*)d_in[3];   // (128,) f32
    float* out = (float*)d_out;                  // (256, 128) f32

    prep_kernel<<<(VOCAB * D_MODEL + 255) / 256, 256>>>(emb);

    cudaFuncSetAttribute(rin_scan_kernel,
                         cudaFuncAttributeMaxDynamicSharedMemorySize, SM_TOTAL);
    rin_scan_kernel<<<BATCH_N / 2, 128, SM_TOTAL>>>(ids, W, bias, out);
}